// round 9
// baseline (speedup 1.0000x reference)
#include <cuda_runtime.h>
#include <math.h>
#include <cstdint>

// ---------------- problem constants ----------------
#define N_TOT   65536      // B*H*W
#define K_CB    512
#define C_DIM   64
#define B_DIM   64
#define HW      1024

#define TM      64         // rows per tile
#define THREADS 512
#define NTILES  1024
#define NCTAS   152        // GB300 SM count; persistent 1 CTA/SM
#define WROW    514        // wT row stride (floats)

// output layout (floats), concatenation of the reference tuple
#define Q_OFF     0ULL
#define LOSS_OFF  4194304ULL
#define PERP_OFF  4194368ULL
#define ENC_OFF   4194369ULL
#define EIDX_OFF  37748801ULL
#define DIST_OFF  37814337ULL
#define OUT_TOTAL 71368769

// smem layout (float indices). wT has 65 rows: row 64 is a prefetch pad.
#define SM_WT   0                      // 65*514 = 33410 -> pad 33412
#define SM_XR   33412                  // raw x tiles: 2 x 4096 floats (double buffer)
#define SM_XSD  (SM_XR + 8192)         // duplicated pairs {x,x}: 4096 float2 = 8192 floats
#define SM_WN   (SM_XSD + 8192)        // wnorm[512]
#define SM_XN   (SM_WN + 512)          // xnorm[64]
#define SM_SIDX (SM_XN + 64)           // int sidx[64]
#define SM_CANB (SM_SIDX + 64)         // float candb[128]
#define SM_CANI (SM_CANB + 128)        // int candi[128]
#define SM_RED  (SM_CANI + 128)        // float red[512]
#define SM_TOTF (SM_RED + 512)
#define SMEM_BYTES (SM_TOTF * 4)       // ~205 KB -> 1 CTA/SM

__device__ float g_lpart[NTILES];
__device__ int   g_hist [K_CB];        // zero at load; last CTA re-zeroes each launch
__device__ int   g_done;               // arrival ticket; last CTA resets

typedef unsigned long long ull;

// ---------------- helpers ----------------
__device__ __forceinline__ void fma2(ull &d, ull a, ull b) {
    asm("fma.rn.f32x2 %0, %1, %2, %3;" : "=l"(d) : "l"(a), "l"(b), "l"(d));
}
__device__ __forceinline__ void unpack2(ull v, float &lo, float &hi) {
    asm("mov.b64 {%0, %1}, %2;" : "=f"(lo), "=f"(hi) : "l"(v));
}
__device__ __forceinline__ uint32_t smem_u32(const void* p) {
    uint32_t a;
    asm("{ .reg .u64 t; cvta.to.shared.u64 t, %1; cvt.u32.u64 %0, t; }" : "=r"(a) : "l"(p));
    return a;
}
#define CP_ASYNC16(sa, gp) asm volatile("cp.async.cg.shared.global [%0], [%1], 16;" :: "r"(sa), "l"(gp))
#define CP_COMMIT()        asm volatile("cp.async.commit_group;" ::: "memory")
#define CP_WAIT1()         asm volatile("cp.async.wait_group 1;" ::: "memory")
#define CP_WAIT0()         asm volatile("cp.async.wait_group 0;" ::: "memory")

// ---------------- single persistent kernel ----------------
extern "C" __global__ void __launch_bounds__(THREADS, 1)
vq_all(const float* __restrict__ inputs, const float* __restrict__ weight,
       float* __restrict__ out)
{
    extern __shared__ float smem[];
    float* wT    = smem + SM_WT;
    float* xsd   = smem + SM_XSD;      // duplicated pairs
    float* wnorm = smem + SM_WN;
    float* xnorm = smem + SM_XN;
    int*   sidx  = (int*)(smem + SM_SIDX);
    float* candb = smem + SM_CANB;
    int*   candi = (int*)(smem + SM_CANI);
    float* red   = smem + SM_RED;

    const uint32_t xr_sa = smem_u32(smem + SM_XR);
    const int tid  = threadIdx.x;
    const int warp = tid >> 5;
    const int lane = tid & 31;
    const int rowg = warp >> 1;
    const int kg   = warp & 1;
    const int kb   = kg * 256 + 2 * lane;     // codes kb + 64*jj + {0,1}
    const int cta  = blockIdx.x;

    // ---- prefetch first x tile (tile index = cta) into raw buffer 0 ----
    {
        const int t0 = cta;
        const float* src = inputs + (size_t)(t0 >> 4) * (C_DIM * HW) + (t0 & 15) * 64;
        for (int i = tid; i < 1024; i += THREADS) {
            int c = i >> 4, ro = (i & 15) * 4;
            CP_ASYNC16(xr_sa + (uint32_t)(c * 64 + ro) * 4, src + (size_t)c * HW + ro);
        }
        CP_COMMIT();
    }

    // ---- one-time: weight transpose + pad + wnorm ----
    for (int i = tid; i < K_CB * C_DIM; i += THREADS) {
        int k = i >> 6, c = i & 63;
        wT[c * WROW + k] = weight[i];
    }
    for (int k = tid; k < K_CB; k += THREADS) wT[64 * WROW + k] = 0.f;
    __syncthreads();
    {
        float s = 0.f;
        #pragma unroll
        for (int c = 0; c < C_DIM; c++) { float w = wT[c * WROW + tid]; s = fmaf(w, w, s); }
        wnorm[tid] = s;
    }

    // ---- persistent tile loop ----
    int buf = 0;
    for (int t = cta; t < NTILES; t += NCTAS) {
        // prefetch next tile into the other raw buffer (clamped -> redundant tile 0)
        {
            int tn = t + NCTAS; if (tn >= NTILES) tn = 0;
            const float* src = inputs + (size_t)(tn >> 4) * (C_DIM * HW) + (tn & 15) * 64;
            uint32_t dst = xr_sa + (uint32_t)((buf ^ 1) * 4096) * 4;
            for (int i = tid; i < 1024; i += THREADS) {
                int c = i >> 4, ro = (i & 15) * 4;
                CP_ASYNC16(dst + (uint32_t)(c * 64 + ro) * 4, src + (size_t)c * HW + ro);
            }
            CP_COMMIT();
        }
        CP_WAIT1();            // oldest group (current buffer) complete
        __syncthreads();

        const float* xrb = smem + SM_XR + buf * 4096;   // raw xs[c][r]

        // duplicate into {x,x} pairs (removes pack MOVs from the mainloop)
        {
            float2* xd = (float2*)xsd;
            #pragma unroll
            for (int i = tid; i < 4096; i += THREADS) {
                float v = xrb[i];
                xd[i] = make_float2(v, v);
            }
        }
        // xnorm (sequential fmaf rounding)
        if (tid < TM) {
            float s = 0.f;
            #pragma unroll
            for (int c = 0; c < C_DIM; c++) { float x = xrb[c * 64 + tid]; s = fmaf(x, x, s); }
            xnorm[tid] = s;
        }
        __syncthreads();

        // ---- mainloop: 8 rows x 8 codes per thread; A via LDS.128 of dup pairs ----
        ull acc[8][4];
        #pragma unroll
        for (int r = 0; r < 8; r++)
            #pragma unroll
            for (int j = 0; j < 4; j++) acc[r][j] = 0ULL;

        const ulonglong2* arow = (const ulonglong2*)xsd + rowg * 4;  // 8 rows = 4 ull2 per c
        const ull* bbase = (const ull*)(wT + kb);

        #pragma unroll 4
        for (int c = 0; c < C_DIM; c++) {
            ull aa[8];
            #pragma unroll
            for (int i = 0; i < 4; i++) {
                ulonglong2 v = arow[c * 32 + i];   // 64 pairs per c = 32 ull2
                aa[2 * i] = v.x; aa[2 * i + 1] = v.y;
            }
            const ull* bp = bbase + (size_t)c * (WROW / 2);
            ull bb[4];
            #pragma unroll
            for (int j = 0; j < 4; j++) bb[j] = bp[32 * j];
            #pragma unroll
            for (int r = 0; r < 8; r++)
                #pragma unroll
                for (int j = 0; j < 4; j++) fma2(acc[r][j], aa[r], bb[j]);
        }

        const int n0   = t * TM;
        const int bimg = t >> 4;
        const int p0   = (t & 15) * 64;

        // ---- epilogue: distances (reference rounding), warp argmin, candidates ----
        const float INF = __int_as_float(0x7f800000);
        #pragma unroll
        for (int r = 0; r < 8; r++) {
            const int row = rowg * 8 + r;
            const int n   = n0 + row;
            const float xn = xnorm[row];

            float best = INF; int bidx = 0;
            float* dptr = out + DIST_OFF + (size_t)n * K_CB + kb;
            #pragma unroll
            for (int j = 0; j < 4; j++) {
                float zlo, zhi; unpack2(acc[r][j], zlo, zhi);
                const int k0 = kb + 64 * j;
                float dlo = (xn + wnorm[k0])     - 2.0f * zlo;
                float dhi = (xn + wnorm[k0 + 1]) - 2.0f * zhi;
                __stcs(dptr + 64 * j,     dlo);     // DIST_OFF odd -> 4B align, scalar
                __stcs(dptr + 64 * j + 1, dhi);
                if (dlo < best) { best = dlo; bidx = k0; }      // ascending k, strict '<'
                if (dhi < best) { best = dhi; bidx = k0 + 1; }  // -> lowest index on ties
            }
            #pragma unroll
            for (int off = 16; off > 0; off >>= 1) {
                float ob = __shfl_xor_sync(0xffffffffu, best, off);
                int   oi = __shfl_xor_sync(0xffffffffu, bidx, off);
                if (ob < best || (ob == best && oi < bidx)) { best = ob; bidx = oi; }
            }
            if (lane == 0) { candb[row * 2 + kg] = best; candi[row * 2 + kg] = bidx; }
        }
        __syncthreads();

        // combine code-half candidates (half0 indices all lower -> tie keeps half0)
        if (tid < TM) {
            float b0 = candb[tid * 2], b1 = candb[tid * 2 + 1];
            int   i0 = candi[tid * 2], i1 = candi[tid * 2 + 1];
            int bi = (b1 < b0) ? i1 : i0;
            sidx[tid] = bi;
            out[EIDX_OFF + (size_t)(n0 + tid)] = (float)bi;
            atomicAdd(&g_hist[bi], 1);            // int atomics: order-independent
        }
        __syncthreads();

        // encodings one-hot rows: vectorized interior (k=3..506 in float4) + 4 scalars
        {
            float* ebase = out + ENC_OFF + (size_t)n0 * K_CB;
            #pragma unroll
            for (int rr = 0; rr < 4; rr++) {
                const int row = warp * 4 + rr;
                const int sv  = sidx[row];
                float* rbase = ebase + (size_t)row * K_CB;
                #pragma unroll
                for (int m = lane; m < 127; m += 32) {
                    const int k = 3 + 4 * m;
                    float4 v;
                    v.x = (sv == k)     ? 1.0f : 0.0f;
                    v.y = (sv == k + 1) ? 1.0f : 0.0f;
                    v.z = (sv == k + 2) ? 1.0f : 0.0f;
                    v.w = (sv == k + 3) ? 1.0f : 0.0f;
                    __stcs((float4*)(rbase + k), v);   // 16B aligned (ENC_OFF odd + 3)
                }
                if (lane < 3)       rbase[lane] = (sv == lane) ? 1.0f : 0.0f;
                else if (lane == 3) rbase[511]  = (sv == 511)  ? 1.0f : 0.0f;
            }
        }

        // q_out (straight-through: x + (q - x)), float4 stores + fused loss partial
        float* qbase = out + (size_t)bimg * (C_DIM * HW) + p0;
        float s = 0.f;
        #pragma unroll
        for (int i = tid; i < 1024; i += THREADS) {
            const int c = i >> 4, p4 = (i & 15) * 4;
            float4 x4 = *(const float4*)(xrb + c * 64 + p4);
            const float* wrow = wT + c * WROW;
            float4 o;
            float d0 = wrow[sidx[p4]]     - x4.x;
            float d1 = wrow[sidx[p4 + 1]] - x4.y;
            float d2 = wrow[sidx[p4 + 2]] - x4.z;
            float d3 = wrow[sidx[p4 + 3]] - x4.w;
            o.x = x4.x + d0; o.y = x4.y + d1; o.z = x4.z + d2; o.w = x4.w + d3;
            __stcs((float4*)(qbase + (size_t)c * HW + p4), o);
            s = fmaf(d0, d0, s); s = fmaf(d1, d1, s);
            s = fmaf(d2, d2, s); s = fmaf(d3, d3, s);
        }
        // loss partial: warp shuffle tree + 16-way combine (deterministic fixed order)
        #pragma unroll
        for (int off = 16; off > 0; off >>= 1) s += __shfl_xor_sync(0xffffffffu, s, off);
        if (lane == 0) red[warp] = s;
        __syncthreads();
        if (warp == 0) {
            float v = (lane < 16) ? red[lane] : 0.f;
            #pragma unroll
            for (int off = 8; off > 0; off >>= 1) v += __shfl_xor_sync(0xffffffffu, v, off);
            if (lane == 0) g_lpart[t] = v;
        }
        __syncthreads();         // protects smem reuse + buffer recycling next iter

        buf ^= 1;
    }
    CP_WAIT0();                  // drain any abandoned prefetch

    // ---- fused finish: last CTA computes loss + perplexity ----
    __shared__ int s_last;
    if (tid == 0) {
        __threadfence();
        int tk = atomicAdd(&g_done, 1);
        s_last = (tk == NCTAS - 1);
    }
    __syncthreads();
    if (s_last) {
        if (tid == 0) g_done = 0;                 // reset for graph replay
        if (tid < B_DIM) {
            float s = 0.f;
            #pragma unroll
            for (int j = 0; j < 16; j++) s += g_lpart[tid * 16 + j];   // fixed order
            out[LOSS_OFF + tid] = 1.25f * (s * (1.0f / 65536.0f));
        }
        int h = g_hist[tid];
        g_hist[tid] = 0;                          // restore zero invariant
        float p = (float)h * (1.0f / 65536.0f);
        red[tid] = -p * logf(p + 1e-10f);
        __syncthreads();
        #pragma unroll
        for (int off = 256; off > 0; off >>= 1) {
            if (tid < off) red[tid] += red[tid + off];
            __syncthreads();
        }
        if (tid == 0) out[PERP_OFF] = expf(red[0]);
    }
}

// ---------------- launch ----------------
extern "C" void kernel_launch(void* const* d_in, const int* in_sizes, int n_in,
                              void* d_out, int out_size)
{
    const float* inputs = (const float*)d_in[0];
    const float* weight = (const float*)d_in[1];
    float* out = (float*)d_out;

    if (out_size != OUT_TOTAL) return;

    cudaFuncSetAttribute(vq_all, cudaFuncAttributeMaxDynamicSharedMemorySize, SMEM_BYTES);

    vq_all<<<NCTAS, THREADS, SMEM_BYTES>>>(inputs, weight, out);
}

// round 10
// speedup vs baseline: 1.1070x; 1.1070x over previous
#include <cuda_runtime.h>
#include <math.h>
#include <cstdint>

// ---------------- problem constants ----------------
#define N_TOT   65536      // B*H*W
#define K_CB    512
#define C_DIM   64
#define B_DIM   64
#define HW      1024

#define TM      64         // rows per tile
#define THREADS 512
#define NTILES  1024
#define NCTAS   152        // GB300 SM count; persistent 1 CTA/SM
#define WROW    514        // wT row stride (floats)

// output layout (floats), concatenation of the reference tuple
#define Q_OFF     0ULL
#define LOSS_OFF  4194304ULL
#define PERP_OFF  4194368ULL
#define ENC_OFF   4194369ULL
#define EIDX_OFF  37748801ULL
#define DIST_OFF  37814337ULL
#define OUT_TOTAL 71368769

// smem layout (float indices). wT has 65 rows: row 64 is a prefetch pad.
#define SM_WT   0                      // 65*514 = 33410 -> pad 33412
#define SM_XR   33412                  // raw x tiles: 2 x 4096 floats (double buffer)
#define SM_WN   (SM_XR + 8192)         // wnorm[512]
#define SM_XN   (SM_WN + 512)          // xnorm[64]
#define SM_SIDX (SM_XN + 64)           // int sidx[64]
#define SM_CANB (SM_SIDX + 64)         // float candb[128]
#define SM_CANI (SM_CANB + 128)        // int candi[128]
#define SM_RED  (SM_CANI + 128)        // float red[512]
#define SM_TOTF (SM_RED + 512)
#define SMEM_BYTES (SM_TOTF * 4)       // ~172 KB -> 1 CTA/SM

__device__ float g_lpart[NTILES];
__device__ int   g_hist [K_CB];        // zero at load; last CTA re-zeroes each launch
__device__ int   g_done;               // arrival ticket; last CTA resets

typedef unsigned long long ull;

// ---------------- helpers ----------------
__device__ __forceinline__ ull pack2(float x) {
    ull r; asm("mov.b64 %0, {%1, %1};" : "=l"(r) : "f"(x)); return r;
}
__device__ __forceinline__ void fma2(ull &d, ull a, ull b) {
    asm("fma.rn.f32x2 %0, %1, %2, %3;" : "=l"(d) : "l"(a), "l"(b), "l"(d));
}
__device__ __forceinline__ void unpack2(ull v, float &lo, float &hi) {
    asm("mov.b64 {%0, %1}, %2;" : "=f"(lo), "=f"(hi) : "l"(v));
}
__device__ __forceinline__ uint32_t smem_u32(const void* p) {
    uint32_t a;
    asm("{ .reg .u64 t; cvta.to.shared.u64 t, %1; cvt.u32.u64 %0, t; }" : "=r"(a) : "l"(p));
    return a;
}
#define CP_ASYNC16(sa, gp) asm volatile("cp.async.cg.shared.global [%0], [%1], 16;" :: "r"(sa), "l"(gp))
#define CP_COMMIT()        asm volatile("cp.async.commit_group;" ::: "memory")
#define CP_WAIT1()         asm volatile("cp.async.wait_group 1;" ::: "memory")
#define CP_WAIT0()         asm volatile("cp.async.wait_group 0;" ::: "memory")

// ---------------- single persistent kernel ----------------
extern "C" __global__ void __launch_bounds__(THREADS, 1)
vq_all(const float* __restrict__ inputs, const float* __restrict__ weight,
       float* __restrict__ out)
{
    extern __shared__ float smem[];
    float* wT    = smem + SM_WT;
    float* wnorm = smem + SM_WN;
    float* xnorm = smem + SM_XN;
    int*   sidx  = (int*)(smem + SM_SIDX);
    float* candb = smem + SM_CANB;
    int*   candi = (int*)(smem + SM_CANI);
    float* red   = smem + SM_RED;

    const uint32_t xr_sa = smem_u32(smem + SM_XR);
    const int tid  = threadIdx.x;
    const int warp = tid >> 5;
    const int lane = tid & 31;
    const int rowg = warp >> 1;
    const int kg   = warp & 1;
    const int kb   = kg * 256 + 2 * lane;     // codes kb + 64*jj + {0,1}
    const int cta  = blockIdx.x;

    // ---- prefetch first x tile (tile index = cta) into raw buffer 0 ----
    {
        const int t0 = cta;
        const float* src = inputs + (size_t)(t0 >> 4) * (C_DIM * HW) + (t0 & 15) * 64;
        for (int i = tid; i < 1024; i += THREADS) {
            int c = i >> 4, ro = (i & 15) * 4;
            CP_ASYNC16(xr_sa + (uint32_t)(c * 64 + ro) * 4, src + (size_t)c * HW + ro);
        }
        CP_COMMIT();
    }

    // ---- one-time: weight transpose + pad + wnorm ----
    for (int i = tid; i < K_CB * C_DIM; i += THREADS) {
        int k = i >> 6, c = i & 63;
        wT[c * WROW + k] = weight[i];
    }
    for (int k = tid; k < K_CB; k += THREADS) wT[64 * WROW + k] = 0.f;
    __syncthreads();
    {
        float s = 0.f;
        #pragma unroll
        for (int c = 0; c < C_DIM; c++) { float w = wT[c * WROW + tid]; s = fmaf(w, w, s); }
        wnorm[tid] = s;
    }

    // ---- persistent tile loop ----
    int buf = 0;
    for (int t = cta; t < NTILES; t += NCTAS) {
        // prefetch next tile into the other raw buffer (clamped -> redundant tile 0)
        {
            int tn = t + NCTAS; if (tn >= NTILES) tn = 0;
            const float* src = inputs + (size_t)(tn >> 4) * (C_DIM * HW) + (tn & 15) * 64;
            uint32_t dst = xr_sa + (uint32_t)((buf ^ 1) * 4096) * 4;
            for (int i = tid; i < 1024; i += THREADS) {
                int c = i >> 4, ro = (i & 15) * 4;
                CP_ASYNC16(dst + (uint32_t)(c * 64 + ro) * 4, src + (size_t)c * HW + ro);
            }
            CP_COMMIT();
        }
        CP_WAIT1();            // oldest group (current buffer) complete
        __syncthreads();

        const float* xrb = smem + SM_XR + buf * 4096;   // raw xs[c][r]

        // xnorm for this tile (sequential fmaf rounding; conflict-free reads)
        if (tid < TM) {
            float s = 0.f;
            #pragma unroll
            for (int c = 0; c < C_DIM; c++) { float x = xrb[c * 64 + tid]; s = fmaf(x, x, s); }
            xnorm[tid] = s;
        }
        __syncthreads();

        // ---- mainloop (round-8 proven form): 8 rows x 8 codes per thread ----
        ull acc[8][4];
        #pragma unroll
        for (int r = 0; r < 8; r++)
            #pragma unroll
            for (int j = 0; j < 4; j++) acc[r][j] = 0ULL;

        const float* arow = xrb + rowg * 8;
        const ull* bbase = (const ull*)(wT + kb);

        #pragma unroll 4
        for (int c = 0; c < C_DIM; c++) {
            const float4 a0 = *(const float4*)(arow + c * 64);
            const float4 a1 = *(const float4*)(arow + c * 64 + 4);
            ull aa[8];
            aa[0] = pack2(a0.x); aa[1] = pack2(a0.y); aa[2] = pack2(a0.z); aa[3] = pack2(a0.w);
            aa[4] = pack2(a1.x); aa[5] = pack2(a1.y); aa[6] = pack2(a1.z); aa[7] = pack2(a1.w);
            const ull* bp = bbase + (size_t)c * (WROW / 2);
            ull bb[4];
            #pragma unroll
            for (int j = 0; j < 4; j++) bb[j] = bp[32 * j];
            #pragma unroll
            for (int r = 0; r < 8; r++)
                #pragma unroll
                for (int j = 0; j < 4; j++) fma2(acc[r][j], aa[r], bb[j]);
        }

        const int n0   = t * TM;
        const int bimg = t >> 4;
        const int p0   = (t & 15) * 64;

        // ---- epilogue: distances (reference rounding), warp argmin, candidates ----
        const float INF = __int_as_float(0x7f800000);
        #pragma unroll
        for (int r = 0; r < 8; r++) {
            const int row = rowg * 8 + r;
            const int n   = n0 + row;
            const float xn = xnorm[row];

            float best = INF; int bidx = 0;
            float* dptr = out + DIST_OFF + (size_t)n * K_CB + kb;
            #pragma unroll
            for (int j = 0; j < 4; j++) {
                float zlo, zhi; unpack2(acc[r][j], zlo, zhi);
                const int k0 = kb + 64 * j;
                float dlo = (xn + wnorm[k0])     - 2.0f * zlo;
                float dhi = (xn + wnorm[k0 + 1]) - 2.0f * zhi;
                __stcs(dptr + 64 * j,     dlo);     // DIST_OFF odd -> 4B align, scalar
                __stcs(dptr + 64 * j + 1, dhi);
                if (dlo < best) { best = dlo; bidx = k0; }      // ascending k, strict '<'
                if (dhi < best) { best = dhi; bidx = k0 + 1; }  // -> lowest index on ties
            }
            #pragma unroll
            for (int off = 16; off > 0; off >>= 1) {
                float ob = __shfl_xor_sync(0xffffffffu, best, off);
                int   oi = __shfl_xor_sync(0xffffffffu, bidx, off);
                if (ob < best || (ob == best && oi < bidx)) { best = ob; bidx = oi; }
            }
            if (lane == 0) { candb[row * 2 + kg] = best; candi[row * 2 + kg] = bidx; }
        }
        __syncthreads();

        // combine code-half candidates (half0 indices all lower -> tie keeps half0)
        if (tid < TM) {
            float b0 = candb[tid * 2], b1 = candb[tid * 2 + 1];
            int   i0 = candi[tid * 2], i1 = candi[tid * 2 + 1];
            int bi = (b1 < b0) ? i1 : i0;
            sidx[tid] = bi;
            out[EIDX_OFF + (size_t)(n0 + tid)] = (float)bi;
            atomicAdd(&g_hist[bi], 1);            // int atomics: order-independent
        }
        __syncthreads();

        // encodings one-hot rows: vectorized interior (k=3..506 in float4) + 4 scalars
        {
            float* ebase = out + ENC_OFF + (size_t)n0 * K_CB;
            #pragma unroll
            for (int rr = 0; rr < 4; rr++) {
                const int row = warp * 4 + rr;
                const int sv  = sidx[row];
                float* rbase = ebase + (size_t)row * K_CB;
                #pragma unroll
                for (int m = lane; m < 127; m += 32) {
                    const int k = 3 + 4 * m;
                    float4 v;
                    v.x = (sv == k)     ? 1.0f : 0.0f;
                    v.y = (sv == k + 1) ? 1.0f : 0.0f;
                    v.z = (sv == k + 2) ? 1.0f : 0.0f;
                    v.w = (sv == k + 3) ? 1.0f : 0.0f;
                    __stcs((float4*)(rbase + k), v);   // 16B aligned (ENC_OFF odd + 3)
                }
                if (lane < 3)       rbase[lane] = (sv == lane) ? 1.0f : 0.0f;
                else if (lane == 3) rbase[511]  = (sv == 511)  ? 1.0f : 0.0f;
            }
        }

        // q_out (straight-through: x + (q - x)), float4 stores + fused loss partial
        float* qbase = out + (size_t)bimg * (C_DIM * HW) + p0;
        float s = 0.f;
        #pragma unroll
        for (int i = tid; i < 1024; i += THREADS) {
            const int c = i >> 4, p4 = (i & 15) * 4;
            float4 x4 = *(const float4*)(xrb + c * 64 + p4);
            const float* wrow = wT + c * WROW;
            float4 o;
            float d0 = wrow[sidx[p4]]     - x4.x;
            float d1 = wrow[sidx[p4 + 1]] - x4.y;
            float d2 = wrow[sidx[p4 + 2]] - x4.z;
            float d3 = wrow[sidx[p4 + 3]] - x4.w;
            o.x = x4.x + d0; o.y = x4.y + d1; o.z = x4.z + d2; o.w = x4.w + d3;
            __stcs((float4*)(qbase + (size_t)c * HW + p4), o);
            s = fmaf(d0, d0, s); s = fmaf(d1, d1, s);
            s = fmaf(d2, d2, s); s = fmaf(d3, d3, s);
        }
        // loss partial: warp shuffle tree + 16-way combine (deterministic fixed order)
        #pragma unroll
        for (int off = 16; off > 0; off >>= 1) s += __shfl_xor_sync(0xffffffffu, s, off);
        if (lane == 0) red[warp] = s;
        __syncthreads();
        if (warp == 0) {
            float v = (lane < 16) ? red[lane] : 0.f;
            #pragma unroll
            for (int off = 8; off > 0; off >>= 1) v += __shfl_xor_sync(0xffffffffu, v, off);
            if (lane == 0) g_lpart[t] = v;
        }
        __syncthreads();         // protects smem reuse + buffer recycling next iter

        buf ^= 1;
    }
    CP_WAIT0();                  // drain any abandoned prefetch

    // ---- fused finish: last CTA computes loss + perplexity ----
    __shared__ int s_last;
    if (tid == 0) {
        __threadfence();
        int tk = atomicAdd(&g_done, 1);
        s_last = (tk == NCTAS - 1);
    }
    __syncthreads();
    if (s_last) {
        if (tid == 0) g_done = 0;                 // reset for graph replay
        if (tid < B_DIM) {
            float s = 0.f;
            #pragma unroll
            for (int j = 0; j < 16; j++) s += g_lpart[tid * 16 + j];   // fixed order
            out[LOSS_OFF + tid] = 1.25f * (s * (1.0f / 65536.0f));
        }
        int h = g_hist[tid];
        g_hist[tid] = 0;                          // restore zero invariant
        float p = (float)h * (1.0f / 65536.0f);
        red[tid] = -p * logf(p + 1e-10f);
        __syncthreads();
        #pragma unroll
        for (int off = 256; off > 0; off >>= 1) {
            if (tid < off) red[tid] += red[tid + off];
            __syncthreads();
        }
        if (tid == 0) out[PERP_OFF] = expf(red[0]);
    }
}

// ---------------- launch ----------------
extern "C" void kernel_launch(void* const* d_in, const int* in_sizes, int n_in,
                              void* d_out, int out_size)
{
    const float* inputs = (const float*)d_in[0];
    const float* weight = (const float*)d_in[1];
    float* out = (float*)d_out;

    if (out_size != OUT_TOTAL) return;

    cudaFuncSetAttribute(vq_all, cudaFuncAttributeMaxDynamicSharedMemorySize, SMEM_BYTES);

    vq_all<<<NCTAS, THREADS, SMEM_BYTES>>>(inputs, weight, out);
}